// round 16
// baseline (speedup 1.0000x reference)
#include <cuda_runtime.h>
#include <cuda_bf16.h>
#include <cuda_fp16.h>
#include <math.h>
#include <stdint.h>

#define BQ    2
#define TT    1024
#define HIDD  2048
#define NH    16
#define DKD   128
#define DVD   128
#define MROWS 2048   // BQ*TT

// =================== scratch (device globals; no allocation) ===============
__device__ __align__(16) float g_qpre[MROWS * HIDD];
__device__ __align__(16) float g_kpre[MROWS * HIDD];
__device__ __align__(16) float g_vpre[MROWS * HIDD];
__device__ __align__(16) float g_q[MROWS * HIDD];
__device__ __align__(16) float g_k[MROWS * HIDD];
__device__ __align__(16) float g_v[MROWS * HIDD];
__device__ __align__(16) float g_egf[MROWS * HIDD];
__device__ __align__(16) float g_egs[MROWS * HIDD];
__device__ __align__(16) float g_gbp[MROWS * 128];
__device__ __align__(16) float g_gdp[MROWS * 128];
__device__ __align__(16) float g_g1p[MROWS * 128];
__device__ __align__(16) float g_gate[MROWS * HIDD];
__device__ __align__(16) float g_bf[MROWS * NH];
__device__ __align__(16) float g_bs[MROWS * NH];
__device__ __align__(16) float g_lm[MROWS * NH];
__device__ __align__(16) float g_ost[2 * MROWS * HIDD];
__device__ __align__(16) float g_WT[3 * NH * HIDD];

// bf16 hi/lo splits (gate path)
__device__ __align__(16) __nv_bfloat16 g_xh[MROWS * HIDD];
__device__ __align__(16) __nv_bfloat16 g_xl[MROWS * HIDD];
__device__ __align__(16) __nv_bfloat16 g_p1h2[MROWS * 256];   // [gb | gd] concat
__device__ __align__(16) __nv_bfloat16 g_p1l2[MROWS * 256];
__device__ __align__(16) __nv_bfloat16 g_p1gh[MROWS * 128];   // g1p
__device__ __align__(16) __nv_bfloat16 g_p1gl[MROWS * 128];
__device__ __align__(16) __nv_bfloat16 g_W1Th[3][128 * HIDD];
__device__ __align__(16) __nv_bfloat16 g_Wg2Th[HIDD * 128];
__device__ __align__(16) __nv_bfloat16 g_Wg2Tl[HIDD * 128];
__device__ __align__(16) __nv_bfloat16 g_W1Tl[3][128 * HIDD];
__device__ __align__(16) __nv_bfloat16 g_Bph[HIDD * 256];     // [Wgb2;+Wgd2]^T
__device__ __align__(16) __nv_bfloat16 g_Bpl[HIDD * 256];
__device__ __align__(16) __nv_bfloat16 g_Bmh[HIDD * 256];     // [Wgb2;-Wgd2]^T
__device__ __align__(16) __nv_bfloat16 g_Bml[HIDD * 256];

// f16 operands
__device__ __align__(16) __half g_xf[MROWS * HIDD];
__device__ __align__(16) __half g_of[MROWS * HIDD];
__device__ __align__(16) __half g_Wqkvf[3][HIDD * HIDD];
__device__ __align__(16) __half g_Wof[HIDD * HIDD];

// =================== software transcendentals (FMA pipe) ===================
__device__ __forceinline__ float exp2p(float x) {
    x = fmaxf(fminf(x, 126.f), -126.f);
    float xr = rintf(x);
    float r = x - xr;
    float p = 1.f + r * (0.69314718f + r * (0.24022651f + r * (0.05550411f +
              r * (0.00961813f + r * (0.00133336f + r * 1.54035e-4f)))));
    return __int_as_float(__float_as_int(p) + ((int)xr << 23));
}
__device__ __forceinline__ float log2_1p_exp2(float u) {
    u = fmaxf(fminf(u, 60.f), -60.f);
    if (u > 24.f) return u;
    float t = exp2p(u);
    float y = 1.f + t;
    int i = __float_as_int(y);
    int e = ((i >> 23) & 255) - 127;
    float m = __int_as_float((i & 0x007fffff) | 0x3f800000);
    if (m > 1.4142135f) { m *= 0.5f; e += 1; }
    float d = m + 1.f;
    float rc = __int_as_float(0x7EF311C3 - __float_as_int(d));
    rc = rc * (2.f - d * rc);
    rc = rc * (2.f - d * rc);
    rc = rc * (2.f - d * rc);
    float z = (m - 1.f) * rc;
    float z2 = z * z;
    float lm = 2.885390082f * z * (1.f + z2 * (0.33333333f + z2 * (0.2f + z2 * 0.14285714f)));
    return (float)e + lm;
}
__device__ __forceinline__ float fast_sigmoid(float y) {
    float t = exp2p(-y * 1.44269504f);
    float d = 1.f + t;
    float rc = __int_as_float(0x7EF311C3 - __float_as_int(d));
    rc = rc * (2.f - d * rc);
    rc = rc * (2.f - d * rc);
    rc = rc * (2.f - d * rc);
    return rc;
}

// =================== f32x2 packed helpers ==================================
__device__ __forceinline__ uint64_t f2_pack(float lo, float hi) {
    uint64_t r; asm("mov.b64 %0, {%1,%2};" : "=l"(r) : "f"(lo), "f"(hi)); return r;
}
__device__ __forceinline__ void f2_unpack(uint64_t v, float& lo, float& hi) {
    asm("mov.b64 {%0,%1}, %2;" : "=f"(lo), "=f"(hi) : "l"(v));
}
__device__ __forceinline__ uint64_t f2_mul(uint64_t a, uint64_t b) {
    uint64_t r; asm("mul.rn.f32x2 %0, %1, %2;" : "=l"(r) : "l"(a), "l"(b)); return r;
}
__device__ __forceinline__ uint64_t f2_fma(uint64_t a, uint64_t b, uint64_t c) {
    uint64_t r; asm("fma.rn.f32x2 %0, %1, %2, %3;" : "=l"(r) : "l"(a), "l"(b), "l"(c)); return r;
}

// =================== warp-MMA primitives ===================================
__device__ __forceinline__ void mma16816(float* c, const uint32_t* a, const uint32_t* b) {
    asm volatile(
        "mma.sync.aligned.m16n8k16.row.col.f32.bf16.bf16.f32 "
        "{%0,%1,%2,%3}, {%4,%5,%6,%7}, {%8,%9}, {%0,%1,%2,%3};"
        : "+f"(c[0]), "+f"(c[1]), "+f"(c[2]), "+f"(c[3])
        : "r"(a[0]), "r"(a[1]), "r"(a[2]), "r"(a[3]), "r"(b[0]), "r"(b[1]));
}
__device__ __forceinline__ void mma16816h(float* c, const uint32_t* a, const uint32_t* b) {
    asm volatile(
        "mma.sync.aligned.m16n8k16.row.col.f32.f16.f16.f32 "
        "{%0,%1,%2,%3}, {%4,%5,%6,%7}, {%8,%9}, {%0,%1,%2,%3};"
        : "+f"(c[0]), "+f"(c[1]), "+f"(c[2]), "+f"(c[3])
        : "r"(a[0]), "r"(a[1]), "r"(a[2]), "r"(a[3]), "r"(b[0]), "r"(b[1]));
}
__device__ __forceinline__ void ldsm_x4(uint32_t* r, uint32_t addr) {
    asm volatile("ldmatrix.sync.aligned.m8n8.x4.shared.b16 {%0,%1,%2,%3}, [%4];"
                 : "=r"(r[0]), "=r"(r[1]), "=r"(r[2]), "=r"(r[3]) : "r"(addr));
}
#define CPA16(dst, src) \
    asm volatile("cp.async.cg.shared.global [%0], [%1], 16;" :: "r"(dst), "l"(src))
#define CPA_COMMIT() asm volatile("cp.async.commit_group;" ::: "memory")
#define CPA_WAIT1()  asm volatile("cp.async.wait_group 1;" ::: "memory")
#define CPA_WAIT3()  asm volatile("cp.async.wait_group 3;" ::: "memory")

#define TSTRIDE 40
#define TSTR64  72

// =================== compensated-bf16 HMMA GEMM (gate path) ================
// EPI: 0 = plain (+optional bias), 1 = gates transform exp(-A*softplus(v+db))
struct TcArgs {
    const __nv_bfloat16 *Ah[3], *Al[3], *Bh[3], *Bl[3];
    float *C[3];
    const float *bias[3];
    const float *A_log, *dtb;
    int M, N, K;
};

template<int MI, int NB, int EPI>
__global__ void __launch_bounds__(256, 2) hmma_gemm(const TcArgs args)
{
    constexpr int BM  = MI * 32;
    constexpr int BN  = NB * 64;
    constexpr int NJ  = NB * 2;
    constexpr int ASZ = BM * TSTRIDE * 2;
    constexpr int BSZ = BN * TSTRIDE * 2;

    extern __shared__ __align__(16) char smem[];
    const uint32_t base = (uint32_t)__cvta_generic_to_shared(smem);
    const uint32_t AhU = base;
    const uint32_t AlU = base + 2 * ASZ;
    const uint32_t BhU = base + 4 * ASZ;
    const uint32_t BlU = base + 4 * ASZ + 2 * BSZ;

    const int tid  = threadIdx.x;
    const int wid  = tid >> 5, lane = tid & 31;
    const int wm   = wid >> 2;
    const int wn   = wid & 3;
    const int z    = blockIdx.z;
    const int bm   = blockIdx.y * BM, bn = blockIdx.x * BN;
    const int K    = args.K;
    const __nv_bfloat16* Ah = args.Ah[z];
    const __nv_bfloat16* Al = args.Al[z];
    const __nv_bfloat16* Bh = args.Bh[z];
    const __nv_bfloat16* Bl = args.Bl[z];

    float C[MI][NJ][4];
#pragma unroll
    for (int i = 0; i < MI; i++)
#pragma unroll
        for (int j = 0; j < NJ; j++)
#pragma unroll
            for (int e = 0; e < 4; e++) C[i][j][e] = 0.f;

    const int a_r = (lane & 15);
    const int a_c = (lane >> 4) << 3;
    const int b_r = (lane & 7) + ((lane >> 4) << 3);
    const int b_c = ((lane >> 3) & 1) << 3;

    const int nch = K >> 5;

    auto load_stage = [&](int buf, int k0) {
#pragma unroll 2
        for (int idx = tid; idx < BM * 4; idx += 256) {
            const int row = idx >> 2, c16 = (idx & 3) * 8;
            const uint32_t so = (uint32_t)(row * TSTRIDE + c16) * 2 + buf * ASZ;
            const size_t g = (size_t)(bm + row) * K + k0 + c16;
            CPA16(AhU + so, Ah + g);
            CPA16(AlU + so, Al + g);
        }
#pragma unroll 2
        for (int idx = tid; idx < BN * 4; idx += 256) {
            const int row = idx >> 2, c16 = (idx & 3) * 8;
            const uint32_t so = (uint32_t)(row * TSTRIDE + c16) * 2 + buf * BSZ;
            const size_t g = (size_t)(bn + row) * K + k0 + c16;
            CPA16(BhU + so, Bh + g);
            CPA16(BlU + so, Bl + g);
        }
    };

    load_stage(0, 0);
    CPA_COMMIT();
    if (nch > 1) load_stage(1, 32);
    CPA_COMMIT();

    for (int ch = 0; ch < nch; ch++) {
        CPA_WAIT1();
        __syncthreads();
        const int buf = ch & 1;
        const uint32_t aho = AhU + buf * ASZ, alo = AlU + buf * ASZ;
        const uint32_t bho = BhU + buf * BSZ, blo = BlU + buf * BSZ;
#pragma unroll
        for (int kk = 0; kk < 32; kk += 16) {
            uint32_t afh[MI][4], bfh[NB][4];
#pragma unroll
            for (int mi = 0; mi < MI; mi++) {
                const int r = wm * (MI * 16) + mi * 16 + a_r;
                ldsm_x4(afh[mi], aho + (uint32_t)(r * TSTRIDE + kk + a_c) * 2);
            }
#pragma unroll
            for (int nb = 0; nb < NB; nb++) {
                const int r = wn * (NB * 16) + nb * 16 + b_r;
                ldsm_x4(bfh[nb], bho + (uint32_t)(r * TSTRIDE + kk + b_c) * 2);
            }
#pragma unroll
            for (int mi = 0; mi < MI; mi++)
#pragma unroll
                for (int nj = 0; nj < NJ; nj++)
                    mma16816(C[mi][nj], afh[mi], &bfh[nj >> 1][(nj & 1) * 2]);
            {
                uint32_t afl[MI][4];
#pragma unroll
                for (int mi = 0; mi < MI; mi++) {
                    const int r = wm * (MI * 16) + mi * 16 + a_r;
                    ldsm_x4(afl[mi], alo + (uint32_t)(r * TSTRIDE + kk + a_c) * 2);
                }
#pragma unroll
                for (int mi = 0; mi < MI; mi++)
#pragma unroll
                    for (int nj = 0; nj < NJ; nj++)
                        mma16816(C[mi][nj], afl[mi], &bfh[nj >> 1][(nj & 1) * 2]);
            }
            {
                uint32_t bfl[NB][4];
#pragma unroll
                for (int nb = 0; nb < NB; nb++) {
                    const int r = wn * (NB * 16) + nb * 16 + b_r;
                    ldsm_x4(bfl[nb], blo + (uint32_t)(r * TSTRIDE + kk + b_c) * 2);
                }
#pragma unroll
                for (int mi = 0; mi < MI; mi++)
#pragma unroll
                    for (int nj = 0; nj < NJ; nj++)
                        mma16816(C[mi][nj], afh[mi], &bfl[nj >> 1][(nj & 1) * 2]);
            }
        }
        __syncthreads();
        if (ch + 2 < nch) load_stage(buf, (ch + 2) * 32);
        CPA_COMMIT();
    }

    float* Cg = args.C[z];
    const float* bias = args.bias[z];
    const int N = args.N;
#pragma unroll
    for (int mi = 0; mi < MI; mi++) {
#pragma unroll
        for (int nj = 0; nj < NJ; nj++) {
            const int r0 = bm + wm * (MI * 16) + mi * 16 + (lane >> 2);
            const int c0 = bn + wn * (NB * 16) + nj * 8 + (lane & 3) * 2;
            float v0 = C[mi][nj][0], v1 = C[mi][nj][1];
            float v2 = C[mi][nj][2], v3 = C[mi][nj][3];
            if (EPI == 0) {
                if (bias) {
                    const float b0 = bias[c0], b1 = bias[c0 + 1];
                    v0 += b0; v1 += b1; v2 += b0; v3 += b1;
                }
            } else {
                const float A0 = exp2p(args.A_log[c0 >> 7] * 1.44269504f);
                const float db0 = args.dtb[c0], db1 = args.dtb[c0 + 1];
                v0 = exp2p(-A0 * log2_1p_exp2((v0 + db0) * 1.44269504f));
                v1 = exp2p(-A0 * log2_1p_exp2((v1 + db1) * 1.44269504f));
                v2 = exp2p(-A0 * log2_1p_exp2((v2 + db0) * 1.44269504f));
                v3 = exp2p(-A0 * log2_1p_exp2((v3 + db1) * 1.44269504f));
            }
            *(float2*)(Cg + (size_t)r0 * N + c0)       = make_float2(v0, v1);
            *(float2*)(Cg + (size_t)(r0 + 8) * N + c0) = make_float2(v2, v3);
        }
    }
}

#define SMEM_42 (4 * (128 * TSTRIDE * 2) + 4 * (128 * TSTRIDE * 2))
#define SMEM_21 (4 * (64  * TSTRIDE * 2) + 4 * (64  * TSTRIDE * 2))

// =================== f16 single-pass HMMA GEMM, BK=64 ======================
struct Tc16Args {
    const __half *A[3], *B[3];
    float *C[3];
    int M, N, K;
};

__global__ void __launch_bounds__(256, 2) hmma_gemm_f16(const Tc16Args args)
{
    constexpr int SSZ = 128 * TSTR64 * 2;

    extern __shared__ __align__(16) char smem[];
    const uint32_t base = (uint32_t)__cvta_generic_to_shared(smem);
    const uint32_t AU = base;
    const uint32_t BU = base + 2 * SSZ;

    const int tid  = threadIdx.x;
    const int wid  = tid >> 5, lane = tid & 31;
    const int wm   = wid >> 2;
    const int wn   = wid & 3;
    const int z    = blockIdx.z;
    const int bm   = blockIdx.y * 128, bn = blockIdx.x * 128;
    const int K    = args.K;
    const __half* A = args.A[z];
    const __half* B = args.B[z];

    float C[4][4][4];
#pragma unroll
    for (int i = 0; i < 4; i++)
#pragma unroll
        for (int j = 0; j < 4; j++)
#pragma unroll
            for (int e = 0; e < 4; e++) C[i][j][e] = 0.f;

    const int a_r = (lane & 15);
    const int a_c = (lane >> 4) << 3;
    const int b_r = (lane & 7) + ((lane >> 4) << 3);
    const int b_c = ((lane >> 3) & 1) << 3;

    const int nch = K >> 6;

    auto load_stage = [&](int buf, int k0) {
#pragma unroll 4
        for (int idx = tid; idx < 1024; idx += 256) {
            const int row = idx >> 3, c8 = (idx & 7) * 8;
            const uint32_t so = (uint32_t)(row * TSTR64 + c8) * 2 + buf * SSZ;
            CPA16(AU + so, A + (size_t)(bm + row) * K + k0 + c8);
            CPA16(BU + so, B + (size_t)(bn + row) * K + k0 + c8);
        }
    };

    load_stage(0, 0);
    CPA_COMMIT();
    if (nch > 1) load_stage(1, 64);
    CPA_COMMIT();

    for (int ch = 0; ch < nch; ch++) {
        CPA_WAIT1();
        __syncthreads();
        const int buf = ch & 1;
        const uint32_t ao = AU + buf * SSZ;
        const uint32_t bo = BU + buf * SSZ;
#pragma unroll
        for (int kk = 0; kk < 64; kk += 16) {
            uint32_t af[4][4], bf[2][4];
#pragma unroll
            for (int mi = 0; mi < 4; mi++) {
                const int r = wm * 64 + mi * 16 + a_r;
                ldsm_x4(af[mi], ao + (uint32_t)(r * TSTR64 + kk + a_c) * 2);
            }
#pragma unroll
            for (int nb = 0; nb < 2; nb++) {
                const int r = wn * 32 + nb * 16 + b_r;
                ldsm_x4(bf[nb], bo + (uint32_t)(r * TSTR64 + kk + b_c) * 2);
            }
#pragma unroll
            for (int mi = 0; mi < 4; mi++)
#pragma unroll
                for (int nj = 0; nj < 4; nj++)
                    mma16816h(C[mi][nj], af[mi], &bf[nj >> 1][(nj & 1) * 2]);
        }
        __syncthreads();
        if (ch + 2 < nch) load_stage(buf, (ch + 2) * 64);
        CPA_COMMIT();
    }

    float* Cg = args.C[z];
    const int N = args.N;
#pragma unroll
    for (int mi = 0; mi < 4; mi++) {
#pragma unroll
        for (int nj = 0; nj < 4; nj++) {
            const int r0 = bm + wm * 64 + mi * 16 + (lane >> 2);
            const int c0 = bn + wn * 32 + nj * 8 + (lane & 3) * 2;
            *(float2*)(Cg + (size_t)r0 * N + c0)       = make_float2(C[mi][nj][0], C[mi][nj][1]);
            *(float2*)(Cg + (size_t)(r0 + 8) * N + c0) = make_float2(C[mi][nj][2], C[mi][nj][3]);
        }
    }
}

#define SMEM_F16 (4 * (128 * TSTR64 * 2))

// =================== fused x conversion ====================================
__global__ void convert_xall(const float* __restrict__ s,
                             __half* __restrict__ f,
                             __nv_bfloat16* __restrict__ h,
                             __nv_bfloat16* __restrict__ l, int n)
{
    int i = (blockIdx.x * 256 + threadIdx.x) * 4;
    if (i >= n) return;
    float4 v = *(const float4*)(s + i);
    __half2 f0; f0.x = __float2half_rn(v.x); f0.y = __float2half_rn(v.y);
    __half2 f1; f1.x = __float2half_rn(v.z); f1.y = __float2half_rn(v.w);
    *(__half2*)(f + i)     = f0;
    *(__half2*)(f + i + 2) = f1;
    __nv_bfloat16 h0 = __float2bfloat16(v.x), h1 = __float2bfloat16(v.y);
    __nv_bfloat16 h2 = __float2bfloat16(v.z), h3 = __float2bfloat16(v.w);
    __nv_bfloat162 hh0; hh0.x = h0; hh0.y = h1;
    __nv_bfloat162 hh1; hh1.x = h2; hh1.y = h3;
    *(__nv_bfloat162*)(h + i)     = hh0;
    *(__nv_bfloat162*)(h + i + 2) = hh1;
    __nv_bfloat162 ll0, ll1;
    ll0.x = __float2bfloat16(v.x - __bfloat162float(h0));
    ll0.y = __float2bfloat16(v.y - __bfloat162float(h1));
    ll1.x = __float2bfloat16(v.z - __bfloat162float(h2));
    ll1.y = __float2bfloat16(v.w - __bfloat162float(h3));
    *(__nv_bfloat162*)(l + i)     = ll0;
    *(__nv_bfloat162*)(l + i + 2) = ll1;
}

// g1p -> bf16 hi/lo (stride 128)
__global__ void convert_hilo(const float* __restrict__ s,
                             __nv_bfloat16* __restrict__ h,
                             __nv_bfloat16* __restrict__ l, int n)
{
    int i = (blockIdx.x * 256 + threadIdx.x) * 4;
    if (i >= n) return;
    float4 v = *(const float4*)(s + i);
    __nv_bfloat16 h0 = __float2bfloat16(v.x), h1 = __float2bfloat16(v.y);
    __nv_bfloat16 h2 = __float2bfloat16(v.z), h3 = __float2bfloat16(v.w);
    __nv_bfloat162 hh0; hh0.x = h0; hh0.y = h1;
    __nv_bfloat162 hh1; hh1.x = h2; hh1.y = h3;
    *(__nv_bfloat162*)(h + i)     = hh0;
    *(__nv_bfloat162*)(h + i + 2) = hh1;
    __nv_bfloat162 ll0, ll1;
    ll0.x = __float2bfloat16(v.x - __bfloat162float(h0));
    ll0.y = __float2bfloat16(v.y - __bfloat162float(h1));
    ll1.x = __float2bfloat16(v.z - __bfloat162float(h2));
    ll1.y = __float2bfloat16(v.w - __bfloat162float(h3));
    *(__nv_bfloat162*)(l + i)     = ll0;
    *(__nv_bfloat162*)(l + i + 2) = ll1;
}

// gbp/gdp -> concat [row][256] bf16 hi/lo
__global__ void convert_p1pair(const float* __restrict__ gbp,
                               const float* __restrict__ gdp,
                               __nv_bfloat16* __restrict__ h2,
                               __nv_bfloat16* __restrict__ l2, int n)
{
    int i = (blockIdx.x * 256 + threadIdx.x) * 4;
    if (i >= n) return;
    const int row = i >> 7, col = i & 127;
    float4 b4 = *(const float4*)(gbp + i);
    float4 d4 = *(const float4*)(gdp + i);
    size_t ob = (size_t)row * 256 + col;
    {
        __nv_bfloat16 h0 = __float2bfloat16(b4.x), h1 = __float2bfloat16(b4.y);
        __nv_bfloat16 h2_ = __float2bfloat16(b4.z), h3 = __float2bfloat16(b4.w);
        union { __nv_bfloat16 b[4]; uint2 u; } hp, lp;
        hp.b[0] = h0; hp.b[1] = h1; hp.b[2] = h2_; hp.b[3] = h3;
        lp.b[0] = __float2bfloat16(b4.x - __bfloat162float(h0));
        lp.b[1] = __float2bfloat16(b4.y - __bfloat162float(h1));
        lp.b[2] = __float2bfloat16(b4.z - __bfloat162float(h2_));
        lp.b[3] = __float2bfloat16(b4.w - __bfloat162float(h3));
        *(uint2*)(h2 + ob) = hp.u;
        *(uint2*)(l2 + ob) = lp.u;
    }
    {
        __nv_bfloat16 h0 = __float2bfloat16(d4.x), h1 = __float2bfloat16(d4.y);
        __nv_bfloat16 h2_ = __float2bfloat16(d4.z), h3 = __float2bfloat16(d4.w);
        union { __nv_bfloat16 b[4]; uint2 u; } hp, lp;
        hp.b[0] = h0; hp.b[1] = h1; hp.b[2] = h2_; hp.b[3] = h3;
        lp.b[0] = __float2bfloat16(d4.x - __bfloat162float(h0));
        lp.b[1] = __float2bfloat16(d4.y - __bfloat162float(h1));
        lp.b[2] = __float2bfloat16(d4.z - __bfloat162float(h2_));
        lp.b[3] = __float2bfloat16(d4.w - __bfloat162float(h3));
        *(uint2*)(h2 + ob + 128) = hp.u;
        *(uint2*)(l2 + ob + 128) = lp.u;
    }
}

struct TrArgs {
    const float* src[3];
    __nv_bfloat16 *dh[3], *dl[3];
    int K, N;
};
__global__ void transpose_hilo(const TrArgs a)
{
    __shared__ float tile[32][33];
    const float* W = a.src[blockIdx.z];
    __nv_bfloat16* dh = a.dh[blockIdx.z];
    __nv_bfloat16* dl = a.dl[blockIdx.z];
    const int n0 = blockIdx.x * 32, k0 = blockIdx.y * 32;
    const int tx = threadIdx.x, ty = threadIdx.y;
#pragma unroll
    for (int i = 0; i < 32; i += 8)
        tile[ty + i][tx] = W[(size_t)(k0 + ty + i) * a.N + n0 + tx];
    __syncthreads();
    const int lin   = ty * 32 + tx;
    const int n_loc = lin >> 3;
    const int wc    = (lin & 7) * 4;
    float v0 = tile[wc][n_loc], v1 = tile[wc + 1][n_loc];
    float v2 = tile[wc + 2][n_loc], v3 = tile[wc + 3][n_loc];
    union { __nv_bfloat16 b[4]; uint2 u; } hp, lp;
    hp.b[0] = __float2bfloat16(v0); hp.b[1] = __float2bfloat16(v1);
    hp.b[2] = __float2bfloat16(v2); hp.b[3] = __float2bfloat16(v3);
    lp.b[0] = __float2bfloat16(v0 - __bfloat162float(hp.b[0]));
    lp.b[1] = __float2bfloat16(v1 - __bfloat162float(hp.b[1]));
    lp.b[2] = __float2bfloat16(v2 - __bfloat162float(hp.b[2]));
    lp.b[3] = __float2bfloat16(v3 - __bfloat162float(hp.b[3]));
    size_t o = (size_t)(n0 + n_loc) * a.K + k0 + wc;
    *(uint2*)(dh + o) = hp.u;
    *(uint2*)(dl + o) = lp.u;
}

// [Wgb2;±Wgd2]^T -> Bp/Bm [2048][256] bf16 hi/lo
__global__ void transpose_w2gates(const float* __restrict__ Wgb2,
                                  const float* __restrict__ Wgd2,
                                  __nv_bfloat16* __restrict__ Bph,
                                  __nv_bfloat16* __restrict__ Bpl,
                                  __nv_bfloat16* __restrict__ Bmh,
                                  __nv_bfloat16* __restrict__ Bml)
{
    __shared__ float tile[32][33];
    const float* W = blockIdx.z ? Wgd2 : Wgb2;   // [128][2048]
    const int n0 = blockIdx.x * 32, k0 = blockIdx.y * 32;
    const int tx = threadIdx.x, ty = threadIdx.y;
#pragma unroll
    for (int i = 0; i < 32; i += 8)
        tile[ty + i][tx] = W[(size_t)(k0 + ty + i) * HIDD + n0 + tx];
    __syncthreads();
    const int lin   = ty * 32 + tx;
    const int n_loc = lin >> 3;
    const int wc    = (lin & 7) * 4;
    float v0 = tile[wc][n_loc], v1 = tile[wc + 1][n_loc];
    float v2 = tile[wc + 2][n_loc], v3 = tile[wc + 3][n_loc];
    union { __nv_bfloat16 b[4]; uint2 u; } hp, lp;
    hp.b[0] = __float2bfloat16(v0); hp.b[1] = __float2bfloat16(v1);
    hp.b[2] = __float2bfloat16(v2); hp.b[3] = __float2bfloat16(v3);
    lp.b[0] = __float2bfloat16(v0 - __bfloat162float(hp.b[0]));
    lp.b[1] = __float2bfloat16(v1 - __bfloat162float(hp.b[1]));
    lp.b[2] = __float2bfloat16(v2 - __bfloat162float(hp.b[2]));
    lp.b[3] = __float2bfloat16(v3 - __bfloat162float(hp.b[3]));
    const size_t o = (size_t)(n0 + n_loc) * 256 + blockIdx.z * 128 + k0 + wc;
    *(uint2*)(Bph + o) = hp.u;
    *(uint2*)(Bpl + o) = lp.u;
    uint2 hn = hp.u, ln = lp.u;
    if (blockIdx.z) {   // negate gd half for B-
        hn.x ^= 0x80008000u; hn.y ^= 0x80008000u;
        ln.x ^= 0x80008000u; ln.y ^= 0x80008000u;
    }
    *(uint2*)(Bmh + o) = hn;
    *(uint2*)(Bml + o) = ln;
}

struct TrHArgs {
    const float* src[3];
    __half* d[3];
    int K, N;
};
__global__ void transpose_h(const TrHArgs a)
{
    __shared__ float tile[32][33];
    const float* W = a.src[blockIdx.z];
    __half* d = a.d[blockIdx.z];
    const int n0 = blockIdx.x * 32, k0 = blockIdx.y * 32;
    const int tx = threadIdx.x, ty = threadIdx.y;
#pragma unroll
    for (int i = 0; i < 32; i += 8)
        tile[ty + i][tx] = W[(size_t)(k0 + ty + i) * a.N + n0 + tx];
    __syncthreads();
    const int lin   = ty * 32 + tx;
    const int n_loc = lin >> 3;
    const int wc    = (lin & 7) * 4;
    union { __half b[4]; uint2 u; } hp;
    hp.b[0] = __float2half_rn(tile[wc][n_loc]);
    hp.b[1] = __float2half_rn(tile[wc + 1][n_loc]);
    hp.b[2] = __float2half_rn(tile[wc + 2][n_loc]);
    hp.b[3] = __float2half_rn(tile[wc + 3][n_loc]);
    size_t o = (size_t)(n0 + n_loc) * a.K + k0 + wc;
    *(uint2*)(d + o) = hp.u;
}

// =================== beta path =============================================
__global__ void transpose_w16(const float* __restrict__ Wbb,
                              const float* __restrict__ Wbd,
                              const float* __restrict__ Wlam,
                              float* __restrict__ WT)
{
    int idx = blockIdx.x * 256 + threadIdx.x;
    if (idx >= 3 * NH * HIDD) return;
    int mat = idx / (NH * HIDD);
    int rem = idx - mat * NH * HIDD;
    int h   = rem >> 11;
    int i   = rem & (HIDD - 1);
    const float* W = (mat == 0) ? Wbb : ((mat == 1) ? Wbd : Wlam);
    WT[idx] = W[(size_t)i * NH + h];
}

// fused dots + sigmoid combine
__global__ void beta_dots(const float* __restrict__ x,
                          const float* __restrict__ WT,
                          float* __restrict__ bf, float* __restrict__ bs,
                          float* __restrict__ lm)
{
    __shared__ __align__(16) float xs[HIDD];
    __shared__ float sdot[48];
    const int row = blockIdx.x;
    const float* xr = x + (size_t)row * HIDD;
    for (int i = threadIdx.x; i < HIDD; i += 256) xs[i] = xr[i];
    __syncthreads();
    const int w = threadIdx.x >> 5, lane = threadIdx.x & 31;
    const float4* xs4 = (const float4*)xs;
    for (int d = w; d < 48; d += 8) {
        const float4* Wc4 = (const float4*)(WT + (size_t)d * HIDD);
        float s = 0.f;
        for (int i = lane; i < HIDD / 4; i += 32) {
            float4 xv = xs4[i];
            float4 wv = Wc4[i];
            s += xv.x * wv.x + xv.y * wv.y + xv.z * wv.z + xv.w * wv.w;
        }
#pragma unroll
        for (int off = 16; off; off >>= 1) s += __shfl_xor_sync(0xffffffffu, s, off);
        if (lane == 0) sdot[d] = s;
    }
    __syncthreads();
    if (threadIdx.x < NH) {
        const int h = threadIdx.x;
        float bb = sdot[h], bd = sdot[16 + h], l = sdot[32 + h];
        bf[row * NH + h] = fast_sigmoid(bb + bd);
        bs[row * NH + h] = fast_sigmoid(bb - bd);
        lm[row * NH + h] = fast_sigmoid(l);
    }
}

// =================== conv + SiLU (+l2norm), warp-autonomous ================
// 1 warp = 4 timesteps, 4 channels/lane (float4). No block syncs.
__global__ void conv_silu_norm(const float* __restrict__ qpre,
                               const float* __restrict__ kpre,
                               const float* __restrict__ vpre,
                               const float* __restrict__ cwq,
                               const float* __restrict__ cwk,
                               const float* __restrict__ cwv,
                               float* __restrict__ qo, float* __restrict__ ko,
                               float* __restrict__ vo)
{
    const int z = blockIdx.z;
    const float* pre = (z == 0) ? qpre : ((z == 1) ? kpre : vpre);
    const float* cw  = (z == 0) ? cwq  : ((z == 1) ? cwk  : cwv);
    float* out       = (z == 0) ? qo   : ((z == 1) ? ko   : vo);

    const int w    = threadIdx.x >> 5;
    const int lane = threadIdx.x & 31;
    const int row0 = blockIdx.x * 16 + w * 4;     // 4 rows per warp, same batch
    const int t0   = row0 & (TT - 1);
    const int h    = blockIdx.y;
    const int c    = h * DKD + lane * 4;

    const float4 Wc0 = *(const float4*)(cw + (size_t)(c + 0) * 4);
    const float4 Wc1 = *(const float4*)(cw + (size_t)(c + 1) * 4);
    const float4 Wc2 = *(const float4*)(cw + (size_t)(c + 2) * 4);
    const float4 Wc3 = *(const float4*)(cw + (size_t)(c + 3) * 4);

    const float* rp = pre + (size_t)row0 * HIDD + c;
    float* op = out + (size_t)row0 * HIDD + c;

    float4 p1, p2, p3;
    if (t0 == 0) {
        p1 = make_float4(0.f, 0.f, 0.f, 0.f); p2 = p1; p3 = p1;
    } else {
        p1 = *(const float4*)(rp - HIDD);
        p2 = *(const float4*)(rp - 2 * (ptrdiff_t)HIDD);
        p3 = *(const float4*)(rp - 3 * (ptrdiff_t)HIDD);
    }

#pragma unroll
    for (int tt = 0; tt < 4; tt++) {
        float4 cur = *(const float4*)(rp + (size_t)tt * HIDD);
        float4 y;
        y.x = Wc0.w * cur.x + Wc0.z * p1.x + Wc0.y * p2.x + Wc0.x * p3.x;
        y.y = Wc1.w * cur.y + Wc1.z * p1.y + Wc1.y * p2.y + Wc1.x * p3.y;
        y.z = Wc2.w * cur.z + Wc2.z * p1.z + Wc2.y * p2.z + Wc2.x * p3.z;
        y.w = Wc3.w * cur.w + Wc3.z * p1.w + Wc3.y * p2.w + Wc3.x * p3.w;
        y.x *= fast_sigmoid(y.x);
        y.y *= fast_sigmoid(y.y);
        y.z *= fast_sigmoid(y.z);
        y.w *= fast_sigmoid(y.w);
        if (z < 2) {
            float ss = y.x * y.x + y.y * y.y + y.z * y.z + y.w * y.w;
#pragma unroll
            for (int off = 16; off; off >>= 1) ss += __shfl_xor_sync(0xffffffffu, ss, off);
            float r = rsqrtf(ss + 1e-6f);
            if (z == 0) r *= 0.08838834764831845f;
            y.x *= r; y.y *= r; y.z *= r; y.w *= r;
        }
        *(float4*)(op + (size_t)tt * HIDD) = y;
        p3 = p2; p2 = p1; p1 = cur;
    }
}

// =================== dual-state delta-rule recurrence (warp-independent) ===
#define RSTG 4
#define WSTF 400
__global__ void __launch_bounds__(128)
recurrence_kernel(const float* __restrict__ q, const float* __restrict__ k,
                  const float* __restrict__ v,
                  const float* __restrict__ egf, const float* __restrict__ egs,
                  const float* __restrict__ bfa, const float* __restrict__ bsa,
                  float* __restrict__ ost)
{
    __shared__ __align__(16) float stage[RSTG][4][WSTF];
    __shared__ float sbeta[TT];

    const int s  = blockIdx.z >> 1;
    const int b  = blockIdx.z & 1;
    const int h  = blockIdx.y;
    const int vb = blockIdx.x;
    const int tid  = threadIdx.x;
    const int w    = tid >> 5;
    const int lane = tid & 31;
    const int vloc = lane >> 2;
    const int sub  = lane & 3;
    const int vcol0 = vb * 32 + w * 8;

    const size_t rowbase = (size_t)b * TT * HIDD + h * DKD;
    const float* kr = k + rowbase;
    const float* qr = q + rowbase;
    const float* er = ((s == 0) ? egf : egs) + rowbase;
    const float* vr = v + rowbase + vcol0;
    const float* bp = ((s == 0) ? bfa : bsa) + (size_t)b * TT * NH + h;
    float* op = ost + (size_t)s * MROWS * HIDD + rowbase + vcol0 + vloc;

    for (int i = tid; i < TT; i += 128) sbeta[i] = bp[(size_t)i * NH];

    const uint32_t wbase = (uint32_t)__cvta_generic_to_shared(&stage[0][w][0]);
    constexpr uint32_t STGB = 4 * WSTF * 4;

    auto load_t = [&](int st, int t) {
        const size_t off = (size_t)t * HIDD;
        const uint32_t sb = wbase + (uint32_t)st * STGB;
        CPA16(sb + lane * 16,        kr + off + lane * 4);
        CPA16(sb + 512 + lane * 16,  er + off + lane * 4);
        CPA16(sb + 1024 + lane * 16, qr + off + lane * 4);
        if (lane < 2) CPA16(sb + 1536 + lane * 16, vr + off + lane * 4);
    };
    load_t(0, 0); CPA_COMMIT();
    load_t(1, 1); CPA_COMMIT();
    load_t(2, 2); CPA_COMMIT();
    load_t(3, 3); CPA_COMMIT();

    __syncthreads();

    uint64_t S[16], kreg[16];
#pragma unroll
    for (int i = 0; i < 16; i++) S[i] = 0ull;

    for (int t = 0; t < TT; t++) {
        CPA_WAIT3();
        __syncwarp();
        const int st = t & (RSTG - 1);
        const float* stw = &stage[st][w][0];

        const ulonglong2* kp2 = (const ulonglong2*)(stw + sub * 32);
        const ulonglong2* ep2 = (const ulonglong2*)(stw + 128 + sub * 32);
        const ulonglong2* qp2 = (const ulonglong2*)(stw + 256 + sub * 32);
        const float vt   = stw[384 + vloc];
        const float beta = sbeta[t];

        uint64_t m0 = 0ull, m1 = 0ull;
#pragma unroll
        for (int j = 0; j < 8; j++) {
            ulonglong2 k2 = kp2[j], e2 = ep2[j];
            uint64_t s0 = f2_mul(S[2 * j],     e2.x);
            uint64_t s1 = f2_mul(S[2 * j + 1], e2.y);
            S[2 * j] = s0; S[2 * j + 1] = s1;
            m0 = f2_fma(k2.x, s0, m0);
            m1 = f2_fma(k2.y, s1, m1);
            kreg[2 * j] = k2.x; kreg[2 * j + 1] = k2.y;
        }
        float a0, a1, b0v, b1v;
        f2_unpack(m0, a0, a1); f2_unpack(m1, b0v, b1v);
        float mem = (a0 + a1) + (b0v + b1v);
        mem += __shfl_xor_sync(0xffffffffu, mem, 1);
        mem += __shfl_xor_sync(0xffffffffu, mem, 2);

        const float u = beta * (vt - mem);
        const uint64_t u2 = f2_pack(u, u);

        uint64_t o0 = 0ull, o1 = 0ull;
#pragma unroll
        for (int j = 0; j < 8; j++) {
            ulonglong2 q2 = qp2[j];
            uint64_t s0 = f2_fma(kreg[2 * j],     u2, S[2 * j]);
            uint64_t s1 = f2_fma(kreg[2 * j + 1], u2, S[2 * j + 1]);
            S[2 * j] = s0; S[2 * j + 1] = s1;
            o0 = f2_fma(q2.x, s0, o0);
            o1 = f2_fma(q2.y, s1, o1);
        }
        f2_unpack(o0, a0, a1); f2_unpack(o1, b0v, b1v);
        float o = (a0 + a1) + (b0v + b1v);
        o += __shfl_xor_sync(0xffffffffu, o, 1);
        o += __shfl_xor_sync(0xffffffffu, o, 2);
        if (sub == 0) op[(size_t)t * HIDD] = o;

        __syncwarp();
        if (t + RSTG < TT) load_t(st, t + RSTG);
        CPA_COMMIT();
    }
}

// =================== mix + gated RMSNorm (writes f16 directly) =============
__global__ void combine_kernel(const float* __restrict__ ost,
                               const float* __restrict__ lm,
                               const float* __restrict__ gate,
                               const float* __restrict__ onw,
                               __half* __restrict__ ofo)
{
    const int row = blockIdx.x;
    const int h   = blockIdx.y;
    const int dv  = threadIdx.x;
    const size_t i0 = (size_t)row * HIDD + h * DKD + dv;
    float of = ost[i0];
    float os = ost[(size_t)MROWS * HIDD + i0];
    float l  = lm[row * NH + h];
    float o  = l * of + (1.f - l) * os;
    __shared__ float red[4];
    float ss = o * o;
#pragma unroll
    for (int off = 16; off; off >>= 1) ss += __shfl_xor_sync(0xffffffffu, ss, off);
    if ((threadIdx.x & 31) == 0) red[threadIdx.x >> 5] = ss;
    __syncthreads();
    float tot = red[0] + red[1] + red[2] + red[3];
    float r = rsqrtf(tot * (1.f / 128.f) + 1e-5f);
    o = o * r * onw[dv];
    o = o * fast_sigmoid(gate[i0]);
    ofo[i0] = __float2half_rn(o);
}

// =================== launch ================================================
extern "C" void kernel_launch(void* const* d_in, const int* in_sizes, int n_in,
                              void* d_out, int out_size)
{
    (void)in_sizes; (void)n_in; (void)out_size;
    const float* x    = (const float*)d_in[0];
    const float* Wq   = (const float*)d_in[1];
    const float* Wk   = (const float*)d_in[2];
    const float* Wv   = (const float*)d_in[3];
    const float* cwq  = (const float*)d_in[4];
    const float* cwk  = (const float*)d_in[5];
    const float* cwv  = (const float*)d_in[6];
    const float* Wgb1 = (const float*)d_in[7];
    const float* Wgb2 = (const float*)d_in[8];
    const float* Wgd1 = (const float*)d_in[9];
    const float* Wgd2 = (const float*)d_in[10];
    const float* Wbb  = (const float*)d_in[11];
    const float* Wbd  = (const float*)d_in[12];
    const float* Wlam = (const float*)d_in[13];
    const float* A_log= (const float*)d_in[14];
    const float* dtb  = (const float*)d_in[15];
    const float* Wg1  = (const float*)d_in[16];
    const float* Wg2  = (const float*)d_in[17];
    const float* bg2  = (const float*)d_in[18];
    const float* onw  = (const float*)d_in[19];
    const float* Wo   = (const float*)d_in[20];
    float* out = (float*)d_out;

    float *qpre, *kpre, *vpre, *q, *k, *v, *egf, *egs;
    float *gbp, *gdp, *g1p, *gate, *bfp, *bsp, *lmp, *ost, *WT;
    cudaGetSymbolAddress((void**)&qpre, g_qpre);
    cudaGetSymbolAddress((void**)&kpre, g_kpre);
    cudaGetSymbolAddress((void**)&vpre, g_vpre);
    cudaGetSymbolAddress((void**)&q,    g_q);
    cudaGetSymbolAddress((void**)&k,    g_k);
    cudaGetSymbolAddress((void**)&v,    g_v);
    cudaGetSymbolAddress((void**)&egf,  g_egf);
    cudaGetSymbolAddress((void**)&egs,  g_egs);
    cudaGetSymbolAddress((void**)&gbp,  g_gbp);
    cudaGetSymbolAddress((void**)&gdp,  g_gdp);
    cudaGetSymbolAddress((void**)&g1p,  g_g1p);
    cudaGetSymbolAddress((void**)&gate, g_gate);
    cudaGetSymbolAddress((void**)&bfp,  g_bf);
    cudaGetSymbolAddress((void**)&bsp,  g_bs);
    cudaGetSymbolAddress((void**)&lmp,  g_lm);
    cudaGetSymbolAddress((void**)&ost,  g_ost);
    cudaGetSymbolAddress((void**)&WT,   g_WT);

    __nv_bfloat16 *xh, *xl, *p1h2, *p1l2, *p1gh, *p1gl;
    __nv_bfloat16 *W1Th, *W1Tl, *Wg2Th, *Wg2Tl, *Bph, *Bpl, *Bmh, *Bml;
    cudaGetSymbolAddress((void**)&xh, g_xh);
    cudaGetSymbolAddress((void**)&xl, g_xl);
    cudaGetSymbolAddress((void**)&p1h2, g_p1h2);
    cudaGetSymbolAddress((void**)&p1l2, g_p1l2);
    cudaGetSymbolAddress((void**)&p1gh, g_p1gh);
    cudaGetSymbolAddress((void**)&p1gl, g_p1gl);
    cudaGetSymbolAddress((void**)&W1Th, g_W1Th);
    cudaGetSymbolAddress((void**)&W1Tl, g_W1Tl);
    cudaGetSymbolAddress((void**)&Wg2Th, g_Wg2Th);
    cudaGetSymbolAddress((void**)&Wg2Tl, g_Wg2Tl);
    cudaGetSymbolAddress((void**)&Bph, g_Bph);
    cudaGetSymbolAddress((void**)&Bpl, g_Bpl);
    cudaGetSymbolAddress((void**)&Bmh, g_Bmh);
    cudaGetSymbolAddress((void**)&Bml, g_Bml);

    __half *xf, *of, *Wqkvf, *Wof;
    cudaGetSymbolAddress((void**)&xf, g_xf);
    cudaGetSymbolAddress((void**)&of, g_of);
    cudaGetSymbolAddress((void**)&Wqkvf, g_Wqkvf);
    cudaGetSymbolAddress((void**)&Wof, g_Wof);

    cudaFuncSetAttribute(hmma_gemm<4,2,0>, cudaFuncAttributeMaxDynamicSharedMemorySize, SMEM_42);
    cudaFuncSetAttribute(hmma_gemm<4,2,1>, cudaFuncAttributeMaxDynamicSharedMemorySize, SMEM_42);
    cudaFuncSetAttribute(hmma_gemm<2,1,0>, cudaFuncAttributeMaxDynamicSharedMemorySize, SMEM_21);
    cudaFuncSetAttribute(hmma_gemm_f16, cudaFuncAttributeMaxDynamicSharedMemorySize, SMEM_F16);

    const size_t SQ = (size_t)HIDD * HIDD;
    const size_t SL = (size_t)128 * HIDD;
    const size_t SP = (size_t)MROWS * 128;

    convert_xall<<<(MROWS * HIDD) / 1024, 256>>>(x, xf, xh, xl, MROWS * HIDD);
    {
        TrHArgs a; a.K = HIDD; a.N = HIDD;
        a.src[0] = Wq; a.src[1] = Wk; a.src[2] = Wv;
        a.d[0] = Wqkvf; a.d[1] = Wqkvf + SQ; a.d[2] = Wqkvf + 2 * SQ;
        transpose_h<<<dim3(64, 64, 3), dim3(32, 8)>>>(a);
    }
    // QKV projections
    {
        Tc16Args a; a.M = MROWS; a.N = HIDD; a.K = HIDD;
        for (int i = 0; i < 3; i++) { a.A[i] = xf; a.B[i] = Wqkvf + i * SQ; }
        a.C[0] = qpre; a.C[1] = kpre; a.C[2] = vpre;
        hmma_gemm_f16<<<dim3(16, 16, 3), 256, SMEM_F16>>>(a);
    }
    {
        TrArgs a; a.K = HIDD; a.N = 128;
        a.src[0] = Wgb1; a.src[1] = Wgd1; a.src[2] = Wg1;
        a.dh[0] = W1Th; a.dh[1] = W1Th + SL; a.dh[2] = W1Th + 2 * SL;
        a.dl[0] = W1Tl; a.dl[1] = W1Tl + SL; a.dl[2] = W1Tl + 2 * SL;
        transpose_hilo<<<dim3(4, 64, 3), dim3(32, 8)>>>(a);
    }
    transpose_w2gates<<<dim3(64, 4, 2), dim3(32, 8)>>>(Wgb2, Wgd2, Bph, Bpl, Bmh, Bml);
    {
        TrArgs a; a.K = 128; a.N = HIDD;
        a.src[0] = Wg2; a.src[1] = Wg2; a.src[2] = Wg2;
        a.dh[0] = Wg2Th; a.dh[1] = Wg2Th; a.dh[2] = Wg2Th;
        a.dl[0] = Wg2Tl; a.dl[1] = Wg2Tl; a.dl[2] = Wg2Tl;
        transpose_hilo<<<dim3(64, 4, 1), dim3(32, 8)>>>(a);
    }
    // stage-1 low-rank (bf16 3-pass)
    {
        TcArgs a; a.M = MROWS; a.N = 128; a.K = HIDD;
        a.A_log = nullptr; a.dtb = nullptr;
        for (int i = 0; i < 3; i++) {
            a.Ah[i] = xh; a.Al[i] = xl;
            a.Bh[i] = W1Th + i * SL; a.Bl[i] = W1Tl + i * SL;
            a.bias[i] = nullptr;
        }
        a.C[0] = gbp; a.C[1] = gdp; a.C[2] = g1p;
        hmma_gemm<2,1,0><<<dim3(2, 32, 3), 256, SMEM_21>>>(a);
    }
    convert_p1pair<<<(int)(SP / 1024), 256>>>(gbp, gdp, p1h2, p1l2, (int)SP);
    convert_hilo<<<(int)(SP / 1024), 256>>>(g1p, p1gh, p1gl, (int)SP);
    // stage-2: decay gates fused (K=256 concat, EPI=1)
    {
        TcArgs a; a.M = MROWS; a.N = HIDD; a.K = 256;
        a.A_log = A_log; a.dtb = dtb;
        for (int i = 0; i < 2; i++) {
            a.Ah[i] = p1h2; a.Al[i] = p1l2;
            a.bias[i] = nullptr;
        }
        a.Bh[0] = Bph; a.Bl[0] = Bpl;
        a.Bh[1] = Bmh; a.Bl[1] = Bml;
        a.Ah[2] = p1h2; a.Al[2] = p1l2; a.Bh[2] = Bph; a.Bl[2] = Bpl;
        a.bias[2] = nullptr;
        a.C[0] = egf; a.C[1] = egs; a.C[2] = egf;
        hmma_gemm<4,2,1><<<dim3(16, 16, 2), 256, SMEM_42>>>(a);
    }
    // stage-2: output gate (K=128, bias)
    {
        TcArgs a; a.M = MROWS; a.N = HIDD; a.K = 128;
        a.A_log = nullptr; a.dtb = nullptr;
        for (int i = 0; i < 3; i++) {
            a.Ah[i] = p1gh; a.Al[i] = p1gl;
            a.Bh[i] = Wg2Th; a.Bl[i] = Wg2Tl;
            a.bias[i] = bg2;
        }
        a.C[0] = gate; a.C[1] = gate; a.C[2] = gate;
        hmma_gemm<4,2,0><<<dim3(16, 16, 1), 256, SMEM_42>>>(a);
    }
    {
        TrHArgs a; a.K = HIDD; a.N = HIDD;
        a.src[0] = Wo; a.src[1] = Wo; a.src[2] = Wo;
        a.d[0] = Wof; a.d[1] = Wof; a.d[2] = Wof;
        transpose_h<<<dim3(64, 64, 1), dim3(32, 8)>>>(a);
    }
    transpose_w16<<<(3 * NH * HIDD + 255) / 256, 256>>>(Wbb, Wbd, Wlam, WT);
    beta_dots<<<MROWS, 256>>>(x, WT, bfp, bsp, lmp);
    conv_silu_norm<<<dim3(MROWS / 16, NH, 3), 128>>>(qpre, kpre, vpre, cwq, cwk, cwv, q, k, v);
    recurrence_kernel<<<dim3(4, NH, 4), 128>>>(q, k, v, egf, egs, bfp, bsp, ost);
    combine_kernel<<<dim3(MROWS, NH), 128>>>(ost, lmp, gate, onw, of);
    {
        Tc16Args a; a.M = MROWS; a.N = HIDD; a.K = HIDD;
        for (int i = 0; i < 3; i++) { a.A[i] = of; a.B[i] = Wof; a.C[i] = out; }
        hmma_gemm_f16<<<dim3(16, 16, 1), 256, SMEM_F16>>>(a);
    }
}

// round 17
// speedup vs baseline: 1.0115x; 1.0115x over previous
#include <cuda_runtime.h>
#include <cuda_bf16.h>
#include <cuda_fp16.h>
#include <math.h>
#include <stdint.h>

#define BQ    2
#define TT    1024
#define HIDD  2048
#define NH    16
#define DKD   128
#define DVD   128
#define MROWS 2048   // BQ*TT

// =================== scratch (device globals; no allocation) ===============
__device__ __align__(16) float g_qpre[MROWS * HIDD];
__device__ __align__(16) float g_kpre[MROWS * HIDD];
__device__ __align__(16) float g_vpre[MROWS * HIDD];
__device__ __align__(16) float g_q[MROWS * HIDD];
__device__ __align__(16) float g_k[MROWS * HIDD];
__device__ __align__(16) float g_v[MROWS * HIDD];
__device__ __align__(16) float g_egf[MROWS * HIDD];
__device__ __align__(16) float g_egs[MROWS * HIDD];
__device__ __align__(16) float g_gbp[MROWS * 128];
__device__ __align__(16) float g_gdp[MROWS * 128];
__device__ __align__(16) float g_g1p[MROWS * 128];
__device__ __align__(16) float g_gate[MROWS * HIDD];
__device__ __align__(16) float g_bf[MROWS * NH];
__device__ __align__(16) float g_bs[MROWS * NH];
__device__ __align__(16) float g_lm[MROWS * NH];
__device__ __align__(16) float g_ost[2 * MROWS * HIDD];
__device__ __align__(16) float g_WT[3 * NH * HIDD];

// bf16 hi/lo splits (gate path only)
__device__ __align__(16) __nv_bfloat16 g_xh[MROWS * HIDD];
__device__ __align__(16) __nv_bfloat16 g_xl[MROWS * HIDD];
__device__ __align__(16) __nv_bfloat16 g_p1h[3][MROWS * 128];
__device__ __align__(16) __nv_bfloat16 g_p1l[3][MROWS * 128];
__device__ __align__(16) __nv_bfloat16 g_W1Th[3][128 * HIDD];
__device__ __align__(16) __nv_bfloat16 g_W1Tl[3][128 * HIDD];
__device__ __align__(16) __nv_bfloat16 g_W2Th[3][HIDD * 128];
__device__ __align__(16) __nv_bfloat16 g_W2Tl[3][HIDD * 128];

// f16 operands
__device__ __align__(16) __half g_xf[MROWS * HIDD];
__device__ __align__(16) __half g_of[MROWS * HIDD];
__device__ __align__(16) __half g_Wqkvf[3][HIDD * HIDD];
__device__ __align__(16) __half g_Wof[HIDD * HIDD];

// =================== software transcendentals (FMA pipe) ===================
__device__ __forceinline__ float exp2p(float x) {
    x = fmaxf(fminf(x, 126.f), -126.f);
    float xr = rintf(x);
    float r = x - xr;
    float p = 1.f + r * (0.69314718f + r * (0.24022651f + r * (0.05550411f +
              r * (0.00961813f + r * (0.00133336f + r * 1.54035e-4f)))));
    return __int_as_float(__float_as_int(p) + ((int)xr << 23));
}
__device__ __forceinline__ float log2_1p_exp2(float u) {
    u = fmaxf(fminf(u, 60.f), -60.f);
    if (u > 24.f) return u;
    float t = exp2p(u);
    float y = 1.f + t;
    int i = __float_as_int(y);
    int e = ((i >> 23) & 255) - 127;
    float m = __int_as_float((i & 0x007fffff) | 0x3f800000);
    if (m > 1.4142135f) { m *= 0.5f; e += 1; }
    float d = m + 1.f;
    float rc = __int_as_float(0x7EF311C3 - __float_as_int(d));
    rc = rc * (2.f - d * rc);
    rc = rc * (2.f - d * rc);
    rc = rc * (2.f - d * rc);
    float z = (m - 1.f) * rc;
    float z2 = z * z;
    float lm = 2.885390082f * z * (1.f + z2 * (0.33333333f + z2 * (0.2f + z2 * 0.14285714f)));
    return (float)e + lm;
}
__device__ __forceinline__ float fast_sigmoid(float y) {
    float t = exp2p(-y * 1.44269504f);
    float d = 1.f + t;
    float rc = __int_as_float(0x7EF311C3 - __float_as_int(d));
    rc = rc * (2.f - d * rc);
    rc = rc * (2.f - d * rc);
    rc = rc * (2.f - d * rc);
    return rc;
}

// =================== f32x2 packed helpers ==================================
__device__ __forceinline__ uint64_t f2_pack(float lo, float hi) {
    uint64_t r; asm("mov.b64 %0, {%1,%2};" : "=l"(r) : "f"(lo), "f"(hi)); return r;
}
__device__ __forceinline__ void f2_unpack(uint64_t v, float& lo, float& hi) {
    asm("mov.b64 {%0,%1}, %2;" : "=f"(lo), "=f"(hi) : "l"(v));
}
__device__ __forceinline__ uint64_t f2_mul(uint64_t a, uint64_t b) {
    uint64_t r; asm("mul.rn.f32x2 %0, %1, %2;" : "=l"(r) : "l"(a), "l"(b)); return r;
}
__device__ __forceinline__ uint64_t f2_fma(uint64_t a, uint64_t b, uint64_t c) {
    uint64_t r; asm("fma.rn.f32x2 %0, %1, %2, %3;" : "=l"(r) : "l"(a), "l"(b), "l"(c)); return r;
}

// =================== warp-MMA primitives ===================================
__device__ __forceinline__ void mma16816(float* c, const uint32_t* a, const uint32_t* b) {
    asm volatile(
        "mma.sync.aligned.m16n8k16.row.col.f32.bf16.bf16.f32 "
        "{%0,%1,%2,%3}, {%4,%5,%6,%7}, {%8,%9}, {%0,%1,%2,%3};"
        : "+f"(c[0]), "+f"(c[1]), "+f"(c[2]), "+f"(c[3])
        : "r"(a[0]), "r"(a[1]), "r"(a[2]), "r"(a[3]), "r"(b[0]), "r"(b[1]));
}
__device__ __forceinline__ void mma16816h(float* c, const uint32_t* a, const uint32_t* b) {
    asm volatile(
        "mma.sync.aligned.m16n8k16.row.col.f32.f16.f16.f32 "
        "{%0,%1,%2,%3}, {%4,%5,%6,%7}, {%8,%9}, {%0,%1,%2,%3};"
        : "+f"(c[0]), "+f"(c[1]), "+f"(c[2]), "+f"(c[3])
        : "r"(a[0]), "r"(a[1]), "r"(a[2]), "r"(a[3]), "r"(b[0]), "r"(b[1]));
}
__device__ __forceinline__ void ldsm_x4(uint32_t* r, uint32_t addr) {
    asm volatile("ldmatrix.sync.aligned.m8n8.x4.shared.b16 {%0,%1,%2,%3}, [%4];"
                 : "=r"(r[0]), "=r"(r[1]), "=r"(r[2]), "=r"(r[3]) : "r"(addr));
}
#define CPA16(dst, src) \
    asm volatile("cp.async.cg.shared.global [%0], [%1], 16;" :: "r"(dst), "l"(src))
#define CPA_COMMIT() asm volatile("cp.async.commit_group;" ::: "memory")
#define CPA_WAIT1()  asm volatile("cp.async.wait_group 1;" ::: "memory")
#define CPA_WAIT3()  asm volatile("cp.async.wait_group 3;" ::: "memory")

#define TSTRIDE 40   // BK=32 + 8 pad (bf16 kernel)
#define TSTR64  72   // BK=64 + 8 pad (f16 kernel)

// =================== compensated-bf16 HMMA GEMM (gate path) ================
struct TcArgs {
    const __nv_bfloat16 *Ah[3], *Al[3], *Bh[3], *Bl[3];
    float *C[3];
    const float *bias[3];
    int M, N, K;
};

template<int MI, int NB>
__global__ void __launch_bounds__(256, 2) hmma_gemm(const TcArgs args)
{
    constexpr int BM  = MI * 32;
    constexpr int BN  = NB * 64;
    constexpr int NJ  = NB * 2;
    constexpr int ASZ = BM * TSTRIDE * 2;
    constexpr int BSZ = BN * TSTRIDE * 2;

    extern __shared__ __align__(16) char smem[];
    const uint32_t base = (uint32_t)__cvta_generic_to_shared(smem);
    const uint32_t AhU = base;
    const uint32_t AlU = base + 2 * ASZ;
    const uint32_t BhU = base + 4 * ASZ;
    const uint32_t BlU = base + 4 * ASZ + 2 * BSZ;

    const int tid  = threadIdx.x;
    const int wid  = tid >> 5, lane = tid & 31;
    const int wm   = wid >> 2;
    const int wn   = wid & 3;
    const int z    = blockIdx.z;
    const int bm   = blockIdx.y * BM, bn = blockIdx.x * BN;
    const int K    = args.K;
    const __nv_bfloat16* Ah = args.Ah[z];
    const __nv_bfloat16* Al = args.Al[z];
    const __nv_bfloat16* Bh = args.Bh[z];
    const __nv_bfloat16* Bl = args.Bl[z];

    float C[MI][NJ][4];
#pragma unroll
    for (int i = 0; i < MI; i++)
#pragma unroll
        for (int j = 0; j < NJ; j++)
#pragma unroll
            for (int e = 0; e < 4; e++) C[i][j][e] = 0.f;

    const int a_r = (lane & 15);
    const int a_c = (lane >> 4) << 3;
    const int b_r = (lane & 7) + ((lane >> 4) << 3);
    const int b_c = ((lane >> 3) & 1) << 3;

    const int nch = K >> 5;

    auto load_stage = [&](int buf, int k0) {
#pragma unroll 2
        for (int idx = tid; idx < BM * 4; idx += 256) {
            const int row = idx >> 2, c16 = (idx & 3) * 8;
            const uint32_t so = (uint32_t)(row * TSTRIDE + c16) * 2 + buf * ASZ;
            const size_t g = (size_t)(bm + row) * K + k0 + c16;
            CPA16(AhU + so, Ah + g);
            CPA16(AlU + so, Al + g);
        }
#pragma unroll 2
        for (int idx = tid; idx < BN * 4; idx += 256) {
            const int row = idx >> 2, c16 = (idx & 3) * 8;
            const uint32_t so = (uint32_t)(row * TSTRIDE + c16) * 2 + buf * BSZ;
            const size_t g = (size_t)(bn + row) * K + k0 + c16;
            CPA16(BhU + so, Bh + g);
            CPA16(BlU + so, Bl + g);
        }
    };

    load_stage(0, 0);
    CPA_COMMIT();
    if (nch > 1) load_stage(1, 32);
    CPA_COMMIT();

    for (int ch = 0; ch < nch; ch++) {
        CPA_WAIT1();
        __syncthreads();
        const int buf = ch & 1;
        const uint32_t aho = AhU + buf * ASZ, alo = AlU + buf * ASZ;
        const uint32_t bho = BhU + buf * BSZ, blo = BlU + buf * BSZ;
#pragma unroll
        for (int kk = 0; kk < 32; kk += 16) {
            uint32_t afh[MI][4], bfh[NB][4];
#pragma unroll
            for (int mi = 0; mi < MI; mi++) {
                const int r = wm * (MI * 16) + mi * 16 + a_r;
                ldsm_x4(afh[mi], aho + (uint32_t)(r * TSTRIDE + kk + a_c) * 2);
            }
#pragma unroll
            for (int nb = 0; nb < NB; nb++) {
                const int r = wn * (NB * 16) + nb * 16 + b_r;
                ldsm_x4(bfh[nb], bho + (uint32_t)(r * TSTRIDE + kk + b_c) * 2);
            }
#pragma unroll
            for (int mi = 0; mi < MI; mi++)
#pragma unroll
                for (int nj = 0; nj < NJ; nj++)
                    mma16816(C[mi][nj], afh[mi], &bfh[nj >> 1][(nj & 1) * 2]);
            {
                uint32_t afl[MI][4];
#pragma unroll
                for (int mi = 0; mi < MI; mi++) {
                    const int r = wm * (MI * 16) + mi * 16 + a_r;
                    ldsm_x4(afl[mi], alo + (uint32_t)(r * TSTRIDE + kk + a_c) * 2);
                }
#pragma unroll
                for (int mi = 0; mi < MI; mi++)
#pragma unroll
                    for (int nj = 0; nj < NJ; nj++)
                        mma16816(C[mi][nj], afl[mi], &bfh[nj >> 1][(nj & 1) * 2]);
            }
            {
                uint32_t bfl[NB][4];
#pragma unroll
                for (int nb = 0; nb < NB; nb++) {
                    const int r = wn * (NB * 16) + nb * 16 + b_r;
                    ldsm_x4(bfl[nb], blo + (uint32_t)(r * TSTRIDE + kk + b_c) * 2);
                }
#pragma unroll
                for (int mi = 0; mi < MI; mi++)
#pragma unroll
                    for (int nj = 0; nj < NJ; nj++)
                        mma16816(C[mi][nj], afh[mi], &bfl[nj >> 1][(nj & 1) * 2]);
            }
        }
        __syncthreads();
        if (ch + 2 < nch) load_stage(buf, (ch + 2) * 32);
        CPA_COMMIT();
    }

    float* Cg = args.C[z];
    const float* bias = args.bias[z];
    const int N = args.N;
#pragma unroll
    for (int mi = 0; mi < MI; mi++) {
#pragma unroll
        for (int nj = 0; nj < NJ; nj++) {
            const int r0 = bm + wm * (MI * 16) + mi * 16 + (lane >> 2);
            const int c0 = bn + wn * (NB * 16) + nj * 8 + (lane & 3) * 2;
            float v0 = C[mi][nj][0], v1 = C[mi][nj][1];
            float v2 = C[mi][nj][2], v3 = C[mi][nj][3];
            if (bias) {
                const float b0 = bias[c0], b1 = bias[c0 + 1];
                v0 += b0; v1 += b1; v2 += b0; v3 += b1;
            }
            *(float2*)(Cg + (size_t)r0 * N + c0)       = make_float2(v0, v1);
            *(float2*)(Cg + (size_t)(r0 + 8) * N + c0) = make_float2(v2, v3);
        }
    }
}

#define SMEM_42 (4 * (128 * TSTRIDE * 2) + 4 * (128 * TSTRIDE * 2))
#define SMEM_21 (4 * (64  * TSTRIDE * 2) + 4 * (64  * TSTRIDE * 2))

// =================== f16 single-pass HMMA GEMM, BK=64 ======================
struct Tc16Args {
    const __half *A[3], *B[3];
    float *C[3];
    int M, N, K;
};

__global__ void __launch_bounds__(256, 2) hmma_gemm_f16(const Tc16Args args)
{
    constexpr int SSZ = 128 * TSTR64 * 2;

    extern __shared__ __align__(16) char smem[];
    const uint32_t base = (uint32_t)__cvta_generic_to_shared(smem);
    const uint32_t AU = base;
    const uint32_t BU = base + 2 * SSZ;

    const int tid  = threadIdx.x;
    const int wid  = tid >> 5, lane = tid & 31;
    const int wm   = wid >> 2;
    const int wn   = wid & 3;
    const int z    = blockIdx.z;
    const int bm   = blockIdx.y * 128, bn = blockIdx.x * 128;
    const int K    = args.K;
    const __half* A = args.A[z];
    const __half* B = args.B[z];

    float C[4][4][4];
#pragma unroll
    for (int i = 0; i < 4; i++)
#pragma unroll
        for (int j = 0; j < 4; j++)
#pragma unroll
            for (int e = 0; e < 4; e++) C[i][j][e] = 0.f;

    const int a_r = (lane & 15);
    const int a_c = (lane >> 4) << 3;
    const int b_r = (lane & 7) + ((lane >> 4) << 3);
    const int b_c = ((lane >> 3) & 1) << 3;

    const int nch = K >> 6;

    auto load_stage = [&](int buf, int k0) {
#pragma unroll 4
        for (int idx = tid; idx < 1024; idx += 256) {
            const int row = idx >> 3, c8 = (idx & 7) * 8;
            const uint32_t so = (uint32_t)(row * TSTR64 + c8) * 2 + buf * SSZ;
            CPA16(AU + so, A + (size_t)(bm + row) * K + k0 + c8);
            CPA16(BU + so, B + (size_t)(bn + row) * K + k0 + c8);
        }
    };

    load_stage(0, 0);
    CPA_COMMIT();
    if (nch > 1) load_stage(1, 64);
    CPA_COMMIT();

    for (int ch = 0; ch < nch; ch++) {
        CPA_WAIT1();
        __syncthreads();
        const int buf = ch & 1;
        const uint32_t ao = AU + buf * SSZ;
        const uint32_t bo = BU + buf * SSZ;
#pragma unroll
        for (int kk = 0; kk < 64; kk += 16) {
            uint32_t af[4][4], bf[2][4];
#pragma unroll
            for (int mi = 0; mi < 4; mi++) {
                const int r = wm * 64 + mi * 16 + a_r;
                ldsm_x4(af[mi], ao + (uint32_t)(r * TSTR64 + kk + a_c) * 2);
            }
#pragma unroll
            for (int nb = 0; nb < 2; nb++) {
                const int r = wn * 32 + nb * 16 + b_r;
                ldsm_x4(bf[nb], bo + (uint32_t)(r * TSTR64 + kk + b_c) * 2);
            }
#pragma unroll
            for (int mi = 0; mi < 4; mi++)
#pragma unroll
                for (int nj = 0; nj < 4; nj++)
                    mma16816h(C[mi][nj], af[mi], &bf[nj >> 1][(nj & 1) * 2]);
        }
        __syncthreads();
        if (ch + 2 < nch) load_stage(buf, (ch + 2) * 64);
        CPA_COMMIT();
    }

    float* Cg = args.C[z];
    const int N = args.N;
#pragma unroll
    for (int mi = 0; mi < 4; mi++) {
#pragma unroll
        for (int nj = 0; nj < 4; nj++) {
            const int r0 = bm + wm * 64 + mi * 16 + (lane >> 2);
            const int c0 = bn + wn * 32 + nj * 8 + (lane & 3) * 2;
            *(float2*)(Cg + (size_t)r0 * N + c0)       = make_float2(C[mi][nj][0], C[mi][nj][1]);
            *(float2*)(Cg + (size_t)(r0 + 8) * N + c0) = make_float2(C[mi][nj][2], C[mi][nj][3]);
        }
    }
}

#define SMEM_F16 (4 * (128 * TSTR64 * 2))

// =================== fused x conversion ====================================
__global__ void convert_xall(const float* __restrict__ s,
                             __half* __restrict__ f,
                             __nv_bfloat16* __restrict__ h,
                             __nv_bfloat16* __restrict__ l, int n)
{
    int i = (blockIdx.x * 256 + threadIdx.x) * 4;
    if (i >= n) return;
    float4 v = *(const float4*)(s + i);
    __half2 f0; f0.x = __float2half_rn(v.x); f0.y = __float2half_rn(v.y);
    __half2 f1; f1.x = __float2half_rn(v.z); f1.y = __float2half_rn(v.w);
    *(__half2*)(f + i)     = f0;
    *(__half2*)(f + i + 2) = f1;
    __nv_bfloat16 h0 = __float2bfloat16(v.x), h1 = __float2bfloat16(v.y);
    __nv_bfloat16 h2 = __float2bfloat16(v.z), h3 = __float2bfloat16(v.w);
    __nv_bfloat162 hh0; hh0.x = h0; hh0.y = h1;
    __nv_bfloat162 hh1; hh1.x = h2; hh1.y = h3;
    *(__nv_bfloat162*)(h + i)     = hh0;
    *(__nv_bfloat162*)(h + i + 2) = hh1;
    __nv_bfloat162 ll0, ll1;
    ll0.x = __float2bfloat16(v.x - __bfloat162float(h0));
    ll0.y = __float2bfloat16(v.y - __bfloat162float(h1));
    ll1.x = __float2bfloat16(v.z - __bfloat162float(h2));
    ll1.y = __float2bfloat16(v.w - __bfloat162float(h3));
    *(__nv_bfloat162*)(l + i)     = ll0;
    *(__nv_bfloat162*)(l + i + 2) = ll1;
}

__global__ void convert_hilo(const float* __restrict__ s,
                             __nv_bfloat16* __restrict__ h,
                             __nv_bfloat16* __restrict__ l, int n)
{
    int i = (blockIdx.x * 256 + threadIdx.x) * 4;
    if (i >= n) return;
    float4 v = *(const float4*)(s + i);
    __nv_bfloat16 h0 = __float2bfloat16(v.x), h1 = __float2bfloat16(v.y);
    __nv_bfloat16 h2 = __float2bfloat16(v.z), h3 = __float2bfloat16(v.w);
    __nv_bfloat162 hh0; hh0.x = h0; hh0.y = h1;
    __nv_bfloat162 hh1; hh1.x = h2; hh1.y = h3;
    *(__nv_bfloat162*)(h + i)     = hh0;
    *(__nv_bfloat162*)(h + i + 2) = hh1;
    __nv_bfloat162 ll0, ll1;
    ll0.x = __float2bfloat16(v.x - __bfloat162float(h0));
    ll0.y = __float2bfloat16(v.y - __bfloat162float(h1));
    ll1.x = __float2bfloat16(v.z - __bfloat162float(h2));
    ll1.y = __float2bfloat16(v.w - __bfloat162float(h3));
    *(__nv_bfloat162*)(l + i)     = ll0;
    *(__nv_bfloat162*)(l + i + 2) = ll1;
}

struct TrArgs {
    const float* src[3];
    __nv_bfloat16 *dh[3], *dl[3];
    int K, N;
};
__global__ void transpose_hilo(const TrArgs a)
{
    __shared__ float tile[32][33];
    const float* W = a.src[blockIdx.z];
    __nv_bfloat16* dh = a.dh[blockIdx.z];
    __nv_bfloat16* dl = a.dl[blockIdx.z];
    const int n0 = blockIdx.x * 32, k0 = blockIdx.y * 32;
    const int tx = threadIdx.x, ty = threadIdx.y;
#pragma unroll
    for (int i = 0; i < 32; i += 8)
        tile[ty + i][tx] = W[(size_t)(k0 + ty + i) * a.N + n0 + tx];
    __syncthreads();
    const int lin   = ty * 32 + tx;
    const int n_loc = lin >> 3;
    const int wc    = (lin & 7) * 4;
    float v0 = tile[wc][n_loc], v1 = tile[wc + 1][n_loc];
    float v2 = tile[wc + 2][n_loc], v3 = tile[wc + 3][n_loc];
    union { __nv_bfloat16 b[4]; uint2 u; } hp, lp;
    hp.b[0] = __float2bfloat16(v0); hp.b[1] = __float2bfloat16(v1);
    hp.b[2] = __float2bfloat16(v2); hp.b[3] = __float2bfloat16(v3);
    lp.b[0] = __float2bfloat16(v0 - __bfloat162float(hp.b[0]));
    lp.b[1] = __float2bfloat16(v1 - __bfloat162float(hp.b[1]));
    lp.b[2] = __float2bfloat16(v2 - __bfloat162float(hp.b[2]));
    lp.b[3] = __float2bfloat16(v3 - __bfloat162float(hp.b[3]));
    size_t o = (size_t)(n0 + n_loc) * a.K + k0 + wc;
    *(uint2*)(dh + o) = hp.u;
    *(uint2*)(dl + o) = lp.u;
}

struct TrHArgs {
    const float* src[3];
    __half* d[3];
    int K, N;
};
__global__ void transpose_h(const TrHArgs a)
{
    __shared__ float tile[32][33];
    const float* W = a.src[blockIdx.z];
    __half* d = a.d[blockIdx.z];
    const int n0 = blockIdx.x * 32, k0 = blockIdx.y * 32;
    const int tx = threadIdx.x, ty = threadIdx.y;
#pragma unroll
    for (int i = 0; i < 32; i += 8)
        tile[ty + i][tx] = W[(size_t)(k0 + ty + i) * a.N + n0 + tx];
    __syncthreads();
    const int lin   = ty * 32 + tx;
    const int n_loc = lin >> 3;
    const int wc    = (lin & 7) * 4;
    union { __half b[4]; uint2 u; } hp;
    hp.b[0] = __float2half_rn(tile[wc][n_loc]);
    hp.b[1] = __float2half_rn(tile[wc + 1][n_loc]);
    hp.b[2] = __float2half_rn(tile[wc + 2][n_loc]);
    hp.b[3] = __float2half_rn(tile[wc + 3][n_loc]);
    size_t o = (size_t)(n0 + n_loc) * a.K + k0 + wc;
    *(uint2*)(d + o) = hp.u;
}

// =================== beta path =============================================
__global__ void transpose_w16(const float* __restrict__ Wbb,
                              const float* __restrict__ Wbd,
                              const float* __restrict__ Wlam,
                              float* __restrict__ WT)
{
    int idx = blockIdx.x * 256 + threadIdx.x;
    if (idx >= 3 * NH * HIDD) return;
    int mat = idx / (NH * HIDD);
    int rem = idx - mat * NH * HIDD;
    int h   = rem >> 11;
    int i   = rem & (HIDD - 1);
    const float* W = (mat == 0) ? Wbb : ((mat == 1) ? Wbd : Wlam);
    WT[idx] = W[(size_t)i * NH + h];
}

// fused dots + sigmoid combine (beta_sig eliminated)
__global__ void beta_dots(const float* __restrict__ x,
                          const float* __restrict__ WT,
                          float* __restrict__ bf, float* __restrict__ bs,
                          float* __restrict__ lm)
{
    __shared__ __align__(16) float xs[HIDD];
    __shared__ float sdot[48];
    const int row = blockIdx.x;
    const float* xr = x + (size_t)row * HIDD;
    for (int i = threadIdx.x; i < HIDD; i += 256) xs[i] = xr[i];
    __syncthreads();
    const int w = threadIdx.x >> 5, lane = threadIdx.x & 31;
    const float4* xs4 = (const float4*)xs;
    for (int d = w; d < 48; d += 8) {
        const float4* Wc4 = (const float4*)(WT + (size_t)d * HIDD);
        float s = 0.f;
        for (int i = lane; i < HIDD / 4; i += 32) {
            float4 xv = xs4[i];
            float4 wv = Wc4[i];
            s += xv.x * wv.x + xv.y * wv.y + xv.z * wv.z + xv.w * wv.w;
        }
#pragma unroll
        for (int off = 16; off; off >>= 1) s += __shfl_xor_sync(0xffffffffu, s, off);
        if (lane == 0) sdot[d] = s;
    }
    __syncthreads();
    if (threadIdx.x < NH) {
        const int h = threadIdx.x;
        float bb = sdot[h], bd = sdot[16 + h], l = sdot[32 + h];
        bf[row * NH + h] = fast_sigmoid(bb + bd);
        bs[row * NH + h] = fast_sigmoid(bb - bd);
        lm[row * NH + h] = fast_sigmoid(l);
    }
}

// =================== conv + SiLU (+l2norm), warp-autonomous ================
// 1 warp = 4 timesteps, 4 channels/lane (float4). No block syncs.
__global__ void conv_silu_norm(const float* __restrict__ qpre,
                               const float* __restrict__ kpre,
                               const float* __restrict__ vpre,
                               const float* __restrict__ cwq,
                               const float* __restrict__ cwk,
                               const float* __restrict__ cwv,
                               float* __restrict__ qo, float* __restrict__ ko,
                               float* __restrict__ vo)
{
    const int z = blockIdx.z;
    const float* pre = (z == 0) ? qpre : ((z == 1) ? kpre : vpre);
    const float* cw  = (z == 0) ? cwq  : ((z == 1) ? cwk  : cwv);
    float* out       = (z == 0) ? qo   : ((z == 1) ? ko   : vo);

    const int w    = threadIdx.x >> 5;
    const int lane = threadIdx.x & 31;
    const int row0 = blockIdx.x * 16 + w * 4;
    const int t0   = row0 & (TT - 1);
    const int h    = blockIdx.y;
    const int c    = h * DKD + lane * 4;

    const float4 Wc0 = *(const float4*)(cw + (size_t)(c + 0) * 4);
    const float4 Wc1 = *(const float4*)(cw + (size_t)(c + 1) * 4);
    const float4 Wc2 = *(const float4*)(cw + (size_t)(c + 2) * 4);
    const float4 Wc3 = *(const float4*)(cw + (size_t)(c + 3) * 4);

    const float* rp = pre + (size_t)row0 * HIDD + c;
    float* op = out + (size_t)row0 * HIDD + c;

    float4 p1, p2, p3;
    if (t0 == 0) {
        p1 = make_float4(0.f, 0.f, 0.f, 0.f); p2 = p1; p3 = p1;
    } else {
        p1 = *(const float4*)(rp - HIDD);
        p2 = *(const float4*)(rp - 2 * (ptrdiff_t)HIDD);
        p3 = *(const float4*)(rp - 3 * (ptrdiff_t)HIDD);
    }

#pragma unroll
    for (int tt = 0; tt < 4; tt++) {
        float4 cur = *(const float4*)(rp + (size_t)tt * HIDD);
        float4 y;
        y.x = Wc0.w * cur.x + Wc0.z * p1.x + Wc0.y * p2.x + Wc0.x * p3.x;
        y.y = Wc1.w * cur.y + Wc1.z * p1.y + Wc1.y * p2.y + Wc1.x * p3.y;
        y.z = Wc2.w * cur.z + Wc2.z * p1.z + Wc2.y * p2.z + Wc2.x * p3.z;
        y.w = Wc3.w * cur.w + Wc3.z * p1.w + Wc3.y * p2.w + Wc3.x * p3.w;
        y.x *= fast_sigmoid(y.x);
        y.y *= fast_sigmoid(y.y);
        y.z *= fast_sigmoid(y.z);
        y.w *= fast_sigmoid(y.w);
        if (z < 2) {
            float ss = y.x * y.x + y.y * y.y + y.z * y.z + y.w * y.w;
#pragma unroll
            for (int off = 16; off; off >>= 1) ss += __shfl_xor_sync(0xffffffffu, ss, off);
            float r = rsqrtf(ss + 1e-6f);
            if (z == 0) r *= 0.08838834764831845f;
            y.x *= r; y.y *= r; y.z *= r; y.w *= r;
        }
        *(float4*)(op + (size_t)tt * HIDD) = y;
        p3 = p2; p2 = p1; p1 = cur;
    }
}

// =================== decay gates (float4 vectorized) =======================
__global__ void gates_kernel(const float* __restrict__ A_log,
                             const float* __restrict__ dt_bias,
                             float* __restrict__ egf, float* __restrict__ egs)
{
    int i4 = (blockIdx.x * 256 + threadIdx.x) * 4;
    if (i4 >= MROWS * HIDD) return;
    float4 gb4 = *(const float4*)(egf + i4);
    float4 gd4 = *(const float4*)(egs + i4);
    int c = i4 & (HIDD - 1);
    int h = c >> 7;
    float A  = exp2p(A_log[h] * 1.44269504f);
    float4 db4 = *(const float4*)(dt_bias + c);
    float4 rf, rs;
    {
        float uf = (gb4.x + gd4.x + db4.x) * 1.44269504f;
        float us = (gb4.x - gd4.x + db4.x) * 1.44269504f;
        rf.x = exp2p(-A * log2_1p_exp2(uf));
        rs.x = exp2p(-A * log2_1p_exp2(us));
    }
    {
        float uf = (gb4.y + gd4.y + db4.y) * 1.44269504f;
        float us = (gb4.y - gd4.y + db4.y) * 1.44269504f;
        rf.y = exp2p(-A * log2_1p_exp2(uf));
        rs.y = exp2p(-A * log2_1p_exp2(us));
    }
    {
        float uf = (gb4.z + gd4.z + db4.z) * 1.44269504f;
        float us = (gb4.z - gd4.z + db4.z) * 1.44269504f;
        rf.z = exp2p(-A * log2_1p_exp2(uf));
        rs.z = exp2p(-A * log2_1p_exp2(us));
    }
    {
        float uf = (gb4.w + gd4.w + db4.w) * 1.44269504f;
        float us = (gb4.w - gd4.w + db4.w) * 1.44269504f;
        rf.w = exp2p(-A * log2_1p_exp2(uf));
        rs.w = exp2p(-A * log2_1p_exp2(us));
    }
    *(float4*)(egf + i4) = rf;
    *(float4*)(egs + i4) = rs;
}

// =================== dual-state delta-rule recurrence (warp-independent) ===
#define RSTG 4
#define WSTF 400
__global__ void __launch_bounds__(128)
recurrence_kernel(const float* __restrict__ q, const float* __restrict__ k,
                  const float* __restrict__ v,
                  const float* __restrict__ egf, const float* __restrict__ egs,
                  const float* __restrict__ bfa, const float* __restrict__ bsa,
                  float* __restrict__ ost)
{
    __shared__ __align__(16) float stage[RSTG][4][WSTF];
    __shared__ float sbeta[TT];

    const int s  = blockIdx.z >> 1;
    const int b  = blockIdx.z & 1;
    const int h  = blockIdx.y;
    const int vb = blockIdx.x;
    const int tid  = threadIdx.x;
    const int w    = tid >> 5;
    const int lane = tid & 31;
    const int vloc = lane >> 2;
    const int sub  = lane & 3;
    const int vcol0 = vb * 32 + w * 8;

    const size_t rowbase = (size_t)b * TT * HIDD + h * DKD;
    const float* kr = k + rowbase;
    const float* qr = q + rowbase;
    const float* er = ((s == 0) ? egf : egs) + rowbase;
    const float* vr = v + rowbase + vcol0;
    const float* bp = ((s == 0) ? bfa : bsa) + (size_t)b * TT * NH + h;
    float* op = ost + (size_t)s * MROWS * HIDD + rowbase + vcol0 + vloc;

    for (int i = tid; i < TT; i += 128) sbeta[i] = bp[(size_t)i * NH];

    const uint32_t wbase = (uint32_t)__cvta_generic_to_shared(&stage[0][w][0]);
    constexpr uint32_t STGB = 4 * WSTF * 4;

    auto load_t = [&](int st, int t) {
        const size_t off = (size_t)t * HIDD;
        const uint32_t sb = wbase + (uint32_t)st * STGB;
        CPA16(sb + lane * 16,        kr + off + lane * 4);
        CPA16(sb + 512 + lane * 16,  er + off + lane * 4);
        CPA16(sb + 1024 + lane * 16, qr + off + lane * 4);
        if (lane < 2) CPA16(sb + 1536 + lane * 16, vr + off + lane * 4);
    };
    load_t(0, 0); CPA_COMMIT();
    load_t(1, 1); CPA_COMMIT();
    load_t(2, 2); CPA_COMMIT();
    load_t(3, 3); CPA_COMMIT();

    __syncthreads();

    uint64_t S[16], kreg[16];
#pragma unroll
    for (int i = 0; i < 16; i++) S[i] = 0ull;

    for (int t = 0; t < TT; t++) {
        CPA_WAIT3();
        __syncwarp();
        const int st = t & (RSTG - 1);
        const float* stw = &stage[st][w][0];

        const ulonglong2* kp2 = (const ulonglong2*)(stw + sub * 32);
        const ulonglong2* ep2 = (const ulonglong2*)(stw + 128 + sub * 32);
        const ulonglong2* qp2 = (const ulonglong2*)(stw + 256 + sub * 32);
        const float vt   = stw[384 + vloc];
        const float beta = sbeta[t];

        uint64_t m0 = 0ull, m1 = 0ull;
#pragma unroll
        for (int j = 0; j < 8; j++) {
            ulonglong2 k2 = kp2[j], e2 = ep2[j];
            uint64_t s0 = f2_mul(S[2 * j],     e2.x);
            uint64_t s1 = f2_mul(S[2 * j + 1], e2.y);
            S[2 * j] = s0; S[2 * j + 1] = s1;
            m0 = f2_fma(k2.x, s0, m0);
            m1 = f2_fma(k2.y, s1, m1);
            kreg[2 * j] = k2.x; kreg[2 * j + 1] = k2.y;
        }
        float a0, a1, b0v, b1v;
        f2_unpack(m0, a0, a1); f2_unpack(m1, b0v, b1v);
        float mem = (a0 + a1) + (b0v + b1v);
        mem += __shfl_xor_sync(0xffffffffu, mem, 1);
        mem += __shfl_xor_sync(0xffffffffu, mem, 2);

        const float u = beta * (vt - mem);
        const uint64_t u2 = f2_pack(u, u);

        uint64_t o0 = 0ull, o1 = 0ull;
#pragma unroll
        for (int j = 0; j < 8; j++) {
            ulonglong2 q2 = qp2[j];
            uint64_t s0 = f2_fma(kreg[2 * j],     u2, S[2 * j]);
            uint64_t s1 = f2_fma(kreg[2 * j + 1], u2, S[2 * j + 1]);
            S[2 * j] = s0; S[2 * j + 1] = s1;
            o0 = f2_fma(q2.x, s0, o0);
            o1 = f2_fma(q2.y, s1, o1);
        }
        f2_unpack(o0, a0, a1); f2_unpack(o1, b0v, b1v);
        float o = (a0 + a1) + (b0v + b1v);
        o += __shfl_xor_sync(0xffffffffu, o, 1);
        o += __shfl_xor_sync(0xffffffffu, o, 2);
        if (sub == 0) op[(size_t)t * HIDD] = o;

        __syncwarp();
        if (t + RSTG < TT) load_t(st, t + RSTG);
        CPA_COMMIT();
    }
}

// =================== mix + gated RMSNorm (writes f16 directly) =============
__global__ void combine_kernel(const float* __restrict__ ost,
                               const float* __restrict__ lm,
                               const float* __restrict__ gate,
                               const float* __restrict__ onw,
                               __half* __restrict__ ofo)
{
    const int row = blockIdx.x;
    const int h   = blockIdx.y;
    const int dv  = threadIdx.x;
    const size_t i0 = (size_t)row * HIDD + h * DKD + dv;
    float of = ost[i0];
    float os = ost[(size_t)MROWS * HIDD + i0];
    float l  = lm[row * NH + h];
    float o  = l * of + (1.f - l) * os;
    __shared__ float red[4];
    float ss = o * o;
#pragma unroll
    for (int off = 16; off; off >>= 1) ss += __shfl_xor_sync(0xffffffffu, ss, off);
    if ((threadIdx.x & 31) == 0) red[threadIdx.x >> 5] = ss;
    __syncthreads();
    float tot = red[0] + red[1] + red[2] + red[3];
    float r = rsqrtf(tot * (1.f / 128.f) + 1e-5f);
    o = o * r * onw[dv];
    o = o * fast_sigmoid(gate[i0]);
    ofo[i0] = __float2half_rn(o);
}

// =================== launch ================================================
extern "C" void kernel_launch(void* const* d_in, const int* in_sizes, int n_in,
                              void* d_out, int out_size)
{
    (void)in_sizes; (void)n_in; (void)out_size;
    const float* x    = (const float*)d_in[0];
    const float* Wq   = (const float*)d_in[1];
    const float* Wk   = (const float*)d_in[2];
    const float* Wv   = (const float*)d_in[3];
    const float* cwq  = (const float*)d_in[4];
    const float* cwk  = (const float*)d_in[5];
    const float* cwv  = (const float*)d_in[6];
    const float* Wgb1 = (const float*)d_in[7];
    const float* Wgb2 = (const float*)d_in[8];
    const float* Wgd1 = (const float*)d_in[9];
    const float* Wgd2 = (const float*)d_in[10];
    const float* Wbb  = (const float*)d_in[11];
    const float* Wbd  = (const float*)d_in[12];
    const float* Wlam = (const float*)d_in[13];
    const float* A_log= (const float*)d_in[14];
    const float* dtb  = (const float*)d_in[15];
    const float* Wg1  = (const float*)d_in[16];
    const float* Wg2  = (const float*)d_in[17];
    const float* bg2  = (const float*)d_in[18];
    const float* onw  = (const float*)d_in[19];
    const float* Wo   = (const float*)d_in[20];
    float* out = (float*)d_out;

    float *qpre, *kpre, *vpre, *q, *k, *v, *egf, *egs;
    float *gbp, *gdp, *g1p, *gate, *bfp, *bsp, *lmp, *ost, *WT;
    cudaGetSymbolAddress((void**)&qpre, g_qpre);
    cudaGetSymbolAddress((void**)&kpre, g_kpre);
    cudaGetSymbolAddress((void**)&vpre, g_vpre);
    cudaGetSymbolAddress((void**)&q,    g_q);
    cudaGetSymbolAddress((void**)&k,    g_k);
    cudaGetSymbolAddress((void**)&v,    g_v);
    cudaGetSymbolAddress((void**)&egf,  g_egf);
    cudaGetSymbolAddress((void**)&egs,  g_egs);
    cudaGetSymbolAddress((void**)&gbp,  g_gbp);
    cudaGetSymbolAddress((void**)&gdp,  g_gdp);
    cudaGetSymbolAddress((void**)&g1p,  g_g1p);
    cudaGetSymbolAddress((void**)&gate, g_gate);
    cudaGetSymbolAddress((void**)&bfp,  g_bf);
    cudaGetSymbolAddress((void**)&bsp,  g_bs);
    cudaGetSymbolAddress((void**)&lmp,  g_lm);
    cudaGetSymbolAddress((void**)&ost,  g_ost);
    cudaGetSymbolAddress((void**)&WT,   g_WT);

    __nv_bfloat16 *xh, *xl, *p1h, *p1l, *W1Th, *W1Tl, *W2Th, *W2Tl;
    cudaGetSymbolAddress((void**)&xh, g_xh);
    cudaGetSymbolAddress((void**)&xl, g_xl);
    cudaGetSymbolAddress((void**)&p1h, g_p1h);
    cudaGetSymbolAddress((void**)&p1l, g_p1l);
    cudaGetSymbolAddress((void**)&W1Th, g_W1Th);
    cudaGetSymbolAddress((void**)&W1Tl, g_W1Tl);
    cudaGetSymbolAddress((void**)&W2Th, g_W2Th);
    cudaGetSymbolAddress((void**)&W2Tl, g_W2Tl);

    __half *xf, *of, *Wqkvf, *Wof;
    cudaGetSymbolAddress((void**)&xf, g_xf);
    cudaGetSymbolAddress((void**)&of, g_of);
    cudaGetSymbolAddress((void**)&Wqkvf, g_Wqkvf);
    cudaGetSymbolAddress((void**)&Wof, g_Wof);

    cudaFuncSetAttribute(hmma_gemm<4,2>, cudaFuncAttributeMaxDynamicSharedMemorySize, SMEM_42);
    cudaFuncSetAttribute(hmma_gemm<2,1>, cudaFuncAttributeMaxDynamicSharedMemorySize, SMEM_21);
    cudaFuncSetAttribute(hmma_gemm_f16, cudaFuncAttributeMaxDynamicSharedMemorySize, SMEM_F16);

    const size_t SQ = (size_t)HIDD * HIDD;
    const size_t SL = (size_t)128 * HIDD;
    const size_t SP = (size_t)MROWS * 128;

    convert_xall<<<(MROWS * HIDD) / 1024, 256>>>(x, xf, xh, xl, MROWS * HIDD);
    {
        TrHArgs a; a.K = HIDD; a.N = HIDD;
        a.src[0] = Wq; a.src[1] = Wk; a.src[2] = Wv;
        a.d[0] = Wqkvf; a.d[1] = Wqkvf + SQ; a.d[2] = Wqkvf + 2 * SQ;
        transpose_h<<<dim3(64, 64, 3), dim3(32, 8)>>>(a);
    }
    {
        Tc16Args a; a.M = MROWS; a.N = HIDD; a.K = HIDD;
        for (int i = 0; i < 3; i++) { a.A[i] = xf; a.B[i] = Wqkvf + i * SQ; }
        a.C[0] = qpre; a.C[1] = kpre; a.C[2] = vpre;
        hmma_gemm_f16<<<dim3(16, 16, 3), 256, SMEM_F16>>>(a);
    }
    {
        TrArgs a; a.K = HIDD; a.N = 128;
        a.src[0] = Wgb1; a.src[1] = Wgd1; a.src[2] = Wg1;
        a.dh[0] = W1Th; a.dh[1] = W1Th + SL; a.dh[2] = W1Th + 2 * SL;
        a.dl[0] = W1Tl; a.dl[1] = W1Tl + SL; a.dl[2] = W1Tl + 2 * SL;
        transpose_hilo<<<dim3(4, 64, 3), dim3(32, 8)>>>(a);
    }
    {
        TrArgs a; a.K = 128; a.N = HIDD;
        a.src[0] = Wgb2; a.src[1] = Wgd2; a.src[2] = Wg2;
        a.dh[0] = W2Th; a.dh[1] = W2Th + SL; a.dh[2] = W2Th + 2 * SL;
        a.dl[0] = W2Tl; a.dl[1] = W2Tl + SL; a.dl[2] = W2Tl + 2 * SL;
        transpose_hilo<<<dim3(64, 4, 3), dim3(32, 8)>>>(a);
    }
    {
        TcArgs a; a.M = MROWS; a.N = 128; a.K = HIDD;
        for (int i = 0; i < 3; i++) {
            a.Ah[i] = xh; a.Al[i] = xl;
            a.Bh[i] = W1Th + i * SL; a.Bl[i] = W1Tl + i * SL;
            a.bias[i] = nullptr;
        }
        a.C[0] = gbp; a.C[1] = gdp; a.C[2] = g1p;
        hmma_gemm<2,1><<<dim3(2, 32, 3), 256, SMEM_21>>>(a);
    }
    convert_hilo<<<(int)(SP / 1024), 256>>>(gbp, p1h, p1l, (int)SP);
    convert_hilo<<<(int)(SP / 1024), 256>>>(gdp, p1h + SP, p1l + SP, (int)SP);
    convert_hilo<<<(int)(SP / 1024), 256>>>(g1p, p1h + 2 * SP, p1l + 2 * SP, (int)SP);
    {
        TcArgs a; a.M = MROWS; a.N = HIDD; a.K = 128;
        for (int i = 0; i < 3; i++) {
            a.Ah[i] = p1h + i * SP; a.Al[i] = p1l + i * SP;
            a.Bh[i] = W2Th + i * SL; a.Bl[i] = W2Tl + i * SL;
            a.bias[i] = nullptr;
        }
        a.bias[2] = bg2;
        a.C[0] = egf; a.C[1] = egs; a.C[2] = gate;
        hmma_gemm<4,2><<<dim3(16, 16, 3), 256, SMEM_42>>>(a);
    }
    {
        TrHArgs a; a.K = HIDD; a.N = HIDD;
        a.src[0] = Wo; a.src[1] = Wo; a.src[2] = Wo;
        a.d[0] = Wof; a.d[1] = Wof; a.d[2] = Wof;
        transpose_h<<<dim3(64, 64, 1), dim3(32, 8)>>>(a);
    }
    transpose_w16<<<(3 * NH * HIDD + 255) / 256, 256>>>(Wbb, Wbd, Wlam, WT);
    beta_dots<<<MROWS, 256>>>(x, WT, bfp, bsp, lmp);
    conv_silu_norm<<<dim3(MROWS / 16, NH, 3), 128>>>(qpre, kpre, vpre, cwq, cwk, cwv, q, k, v);
    gates_kernel<<<(MROWS * HIDD) / 1024, 256>>>(A_log, dtb, egf, egs);
    recurrence_kernel<<<dim3(4, NH, 4), 128>>>(q, k, v, egf, egs, bfp, bsp, ost);
    combine_kernel<<<dim3(MROWS, NH), 128>>>(ost, lmp, gate, onw, of);
    {
        Tc16Args a; a.M = MROWS; a.N = HIDD; a.K = HIDD;
        for (int i = 0; i < 3; i++) { a.A[i] = of; a.B[i] = Wof; a.C[i] = out; }
        hmma_gemm_f16<<<dim3(16, 16, 1), 256, SMEM_F16>>>(a);
    }
}